// round 15
// baseline (speedup 1.0000x reference)
#include <cuda_runtime.h>
#include <cuda_fp16.h>
#include <math.h>
#include <stdint.h>

#define H     24
#define LIMG  2048
#define LIP   512
#define DMOD  3072
#define DIP   1280
#define HD    128
#define LTOT  2560
#define KT    64
#define NIT2  20                // key tiles per split (LTOT/2/KT)
#define SCALE2 0.1275174735772347f
#define ONES2 0x3C003C00u

// ================= scratch =================
__device__ float  g_e[2 * DIP];
__device__ __half g_ipnorm_h[LIP * DIP];
__device__ __half g_Wh[2 * (size_t)DMOD * DIP];
__device__ float  g_ipk_raw[LIP * DMOD];
__device__ __half g_Vh[(size_t)H * LTOT * HD];
__device__ __half g_Qh[(size_t)H * LIMG * HD];
__device__ __half g_Kh[(size_t)H * LTOT * HD];
__device__ __half g_Vth[(size_t)H * HD * LTOT];
__device__ __half g_Oparth[2][(size_t)H * LIMG * HD];  // split-K partial O (fp16, unnormalized)
__device__ float  g_ML[2][(size_t)H * LIMG * 2];       // per-row (m, l)

__device__ __forceinline__ uint32_t s2u(const void* p) {
    uint32_t a;
    asm("{ .reg .u64 t; cvta.to.shared.u64 t, %1; cvt.u32.u64 %0, t; }" : "=r"(a) : "l"(p));
    return a;
}
__device__ __forceinline__ uint32_t pkh(float a, float b) {
    __half2 h = __floats2half2_rn(a, b);
    return *reinterpret_cast<uint32_t*>(&h);
}
__device__ __forceinline__ uint32_t pk2(float lo, float hi) {
    uint32_t d;
    asm("cvt.rn.f16x2.f32 %0, %1, %2;" : "=r"(d) : "f"(hi), "f"(lo));
    return d;
}
__device__ __forceinline__ uint32_t hex2(uint32_t x) {
    uint32_t d;
    asm("ex2.approx.f16x2 %0, %1;" : "=r"(d) : "r"(x));
    return d;
}
__device__ __forceinline__ float ex2(float x) {
    float y;
    asm("ex2.approx.f32 %0, %1;" : "=f"(y) : "f"(x));
    return y;
}
__device__ __forceinline__ void mma_f16(float* c, const uint32_t* a, uint32_t b0, uint32_t b1) {
    asm volatile("mma.sync.aligned.m16n8k16.row.col.f32.f16.f16.f32 "
        "{%0,%1,%2,%3}, {%4,%5,%6,%7}, {%8,%9}, {%0,%1,%2,%3};"
        : "+f"(c[0]), "+f"(c[1]), "+f"(c[2]), "+f"(c[3])
        : "r"(a[0]), "r"(a[1]), "r"(a[2]), "r"(a[3]), "r"(b0), "r"(b1));
}
__device__ __forceinline__ void ldsm4(uint32_t* r, uint32_t addr) {
    asm volatile("ldmatrix.sync.aligned.m8n8.x4.shared.b16 {%0,%1,%2,%3}, [%4];"
        : "=r"(r[0]), "=r"(r[1]), "=r"(r[2]), "=r"(r[3]) : "r"(addr));
}
__device__ __forceinline__ void cp16(uint32_t dst, const void* src) {
    asm volatile("cp.async.cg.shared.global [%0], [%1], 16;" :: "r"(dst), "l"(src));
}

extern __shared__ __align__(16) char dynsm[];

// ================= stage 1: ada ================
__global__ void ada_kernel(const float* __restrict__ t_emb,
                           const float* __restrict__ w_ada,
                           const float* __restrict__ b_ada) {
    int o = blockIdx.x * 8 + (threadIdx.x >> 5);
    int lane = threadIdx.x & 31;
    if (o >= 2 * DIP) return;
    const float* w = w_ada + (size_t)o * DIP;
    float s = 0.f;
    for (int i = lane; i < DIP; i += 32) {
        float t = t_emb[i];
        s += (t / (1.f + expf(-t))) * w[i];
    }
#pragma unroll
    for (int off = 16; off; off >>= 1) s += __shfl_xor_sync(0xffffffffu, s, off);
    if (lane == 0) g_e[o] = s + b_ada[o];
}

// ================= stage 2: AdaLN -> fp16 ================
__global__ void adaln_kernel(const float* __restrict__ ip) {
    int row = blockIdx.x;
    const float* x = ip + (size_t)row * DIP;
    __shared__ float red1[8], red2[8];
    float s = 0.f, s2 = 0.f;
    for (int i = threadIdx.x; i < DIP; i += 256) {
        float v = x[i]; s += v; s2 += v * v;
    }
#pragma unroll
    for (int off = 16; off; off >>= 1) {
        s  += __shfl_xor_sync(0xffffffffu, s, off);
        s2 += __shfl_xor_sync(0xffffffffu, s2, off);
    }
    int w = threadIdx.x >> 5, lane = threadIdx.x & 31;
    if (lane == 0) { red1[w] = s; red2[w] = s2; }
    __syncthreads();
    float ts = 0.f, ts2 = 0.f;
#pragma unroll
    for (int i = 0; i < 8; i++) { ts += red1[i]; ts2 += red2[i]; }
    float mu = ts / DIP;
    float inv = rsqrtf(ts2 / DIP - mu * mu + 1e-6f);
    for (int i = threadIdx.x; i < DIP; i += 256) {
        float xn = (x[i] - mu) * inv;
        g_ipnorm_h[(size_t)row * DIP + i] = __float2half(xn * (1.f + g_e[DIP + i]) + g_e[i]);
    }
}

// ================= stage 2b: weight fp32 -> fp16 ================
__global__ void wconv_kernel(const float* __restrict__ wk, const float* __restrict__ wv) {
    size_t i = ((size_t)blockIdx.x * 256 + threadIdx.x) * 4;
    const float* src = blockIdx.y ? wv : wk;
    __half* dst = g_Wh + (size_t)blockIdx.y * DMOD * DIP;
    float4 f = *(const float4*)(src + i);
    uint2 u = { pkh(f.x, f.y), pkh(f.z, f.w) };
    *(uint2*)(dst + i) = u;
}

// ================= stage 3: fused ip GEMM, 2x4 warp grid =====================
#define GEMM_SMEM 92160

__device__ __forceinline__ void gemm_issue(uint32_t sb, int tid, int bm, int bn,
                                           int ks, int buf) {
#pragma unroll
    for (int n = 0; n < 4; n++) {
        int i = tid + n * 256;
        int row = i >> 3, c = i & 7;
        cp16(sb + buf * 18432 + row * 144 + c * 16,
             g_ipnorm_h + (size_t)(bm + row) * DIP + ks * 64 + c * 8);
    }
#pragma unroll
    for (int n = 0; n < 6; n++) {
        int i = tid + n * 256;
        int row = i >> 3, c = i & 7;
        cp16(sb + 36864 + buf * 27648 + row * 144 + c * 16,
             g_Wh + (size_t)(bn + row) * DIP + ks * 64 + c * 8);
    }
    asm volatile("cp.async.commit_group;");
}

__global__ void __launch_bounds__(256, 1) ip_gemm_h_kernel() {
    const uint32_t sb = s2u(dynsm);
    const int tid = threadIdx.x;
    const int w = tid >> 5, t = tid & 31;
    const int r4 = t >> 2, q4 = t & 3;
    const int wr = w >> 2, wc = w & 3;
    const int bn = blockIdx.x * 192, bm = blockIdx.y * 128;

    gemm_issue(sb, tid, bm, bn, 0, 0);
    gemm_issue(sb, tid, bm, bn, 1, 1);

    float oc[4][6][4] = {};
    const int rowselA = t & 15;
    const int winA = (t >> 4) << 4;
    const int rowselB = (t & 7) + ((t & 16) >> 1);
    const int winB = (t & 8) << 1;

    for (int ks = 0; ks < 20; ks++) {
        const int buf = ks & 1;
        if (ks < 18) asm volatile("cp.async.wait_group 1;");
        else         asm volatile("cp.async.wait_group 0;");
        __syncthreads();
        const uint32_t Ab = sb + buf * 18432;
        const uint32_t Bb = sb + 36864 + buf * 27648;
#pragma unroll
        for (int kb = 0; kb < 4; kb++) {
            uint32_t aa[4][4];
#pragma unroll
            for (int mb = 0; mb < 4; mb++)
                ldsm4(aa[mb], Ab + (wr * 64 + mb * 16 + rowselA) * 144 + kb * 32 + winA);
#pragma unroll
            for (int nb = 0; nb < 3; nb++) {
                uint32_t bb[4];
                ldsm4(bb, Bb + (wc * 48 + nb * 16 + rowselB) * 144 + kb * 32 + winB);
#pragma unroll
                for (int mb = 0; mb < 4; mb++) {
                    mma_f16(oc[mb][2 * nb],     aa[mb], bb[0], bb[1]);
                    mma_f16(oc[mb][2 * nb + 1], aa[mb], bb[2], bb[3]);
                }
            }
        }
        __syncthreads();
        if (ks + 2 < 20) gemm_issue(sb, tid, bm, bn, ks + 2, buf);
        else asm volatile("cp.async.commit_group;");
    }

#pragma unroll
    for (int mb = 0; mb < 4; mb++) {
        const int m_lo = bm + wr * 64 + mb * 16 + r4, m_hi = m_lo + 8;
#pragma unroll
        for (int nbp = 0; nbp < 6; nbp++) {
            int n = bn + wc * 48 + nbp * 8 + q4 * 2;
            if (n < DMOD) {
                float2 vlo = { oc[mb][nbp][0], oc[mb][nbp][1] };
                float2 vhi = { oc[mb][nbp][2], oc[mb][nbp][3] };
                *(float2*)(g_ipk_raw + (size_t)m_lo * DMOD + n) = vlo;
                *(float2*)(g_ipk_raw + (size_t)m_hi * DMOD + n) = vhi;
            } else {
                int nn = n - DMOD;
                int hh = nn >> 7, dd = nn & 127;
                *(uint32_t*)(g_Vh + ((size_t)hh * LTOT + LIMG + m_lo) * HD + dd) =
                    pkh(oc[mb][nbp][0], oc[mb][nbp][1]);
                *(uint32_t*)(g_Vh + ((size_t)hh * LTOT + LIMG + m_hi) * HD + dd) =
                    pkh(oc[mb][nbp][2], oc[mb][nbp][3]);
            }
        }
    }
}

// ================= stage 4: RMS + fp16 pack ================
__device__ __forceinline__ float warp_sum(float s) {
#pragma unroll
    for (int off = 16; off; off >>= 1) s += __shfl_xor_sync(0xffffffffu, s, off);
    return s;
}
__device__ __forceinline__ void st_h4(__half* p, float a, float b, float c, float d) {
    uint2 u = { pkh(a, b), pkh(c, d) };
    *reinterpret_cast<uint2*>(p) = u;
}

__global__ void qkv_rms_kernel(const float* __restrict__ q,
                               const float* __restrict__ k,
                               const float* __restrict__ v,
                               const float* __restrict__ gq,
                               const float* __restrict__ gk) {
    int rid = blockIdx.x * 8 + (threadIdx.x >> 5);
    if (rid >= LIMG * H) return;
    int lane = threadIdx.x & 31;
    int l = rid / H, hh = rid % H;
    size_t src = (size_t)l * DMOD + hh * HD + lane * 4;

    float4 xv = *(const float4*)(q + src);
    float inv = rsqrtf(warp_sum(xv.x*xv.x + xv.y*xv.y + xv.z*xv.z + xv.w*xv.w) / 128.f + 1e-6f) * SCALE2;
    float4 gv = ((const float4*)gq)[lane];
    st_h4(g_Qh + ((size_t)hh * LIMG + l) * HD + lane * 4,
          xv.x*inv*gv.x, xv.y*inv*gv.y, xv.z*inv*gv.z, xv.w*inv*gv.w);

    xv = *(const float4*)(k + src);
    inv = rsqrtf(warp_sum(xv.x*xv.x + xv.y*xv.y + xv.z*xv.z + xv.w*xv.w) / 128.f + 1e-6f);
    gv = ((const float4*)gk)[lane];
    st_h4(g_Kh + ((size_t)hh * LTOT + l) * HD + lane * 4,
          xv.x*inv*gv.x, xv.y*inv*gv.y, xv.z*inv*gv.z, xv.w*inv*gv.w);

    xv = *(const float4*)(v + src);
    st_h4(g_Vh + ((size_t)hh * LTOT + l) * HD + lane * 4, xv.x, xv.y, xv.z, xv.w);
}

__global__ void ipk_rms_kernel(const float* __restrict__ gipk) {
    int rid = blockIdx.x * 8 + (threadIdx.x >> 5);
    if (rid >= LIP * H) return;
    int lane = threadIdx.x & 31;
    int l = rid / H, hh = rid % H;
    float4 xv = *(const float4*)(g_ipk_raw + (size_t)l * DMOD + hh * HD + lane * 4);
    float inv = rsqrtf(warp_sum(xv.x*xv.x + xv.y*xv.y + xv.z*xv.z + xv.w*xv.w) / 128.f + 1e-6f);
    float4 gv = ((const float4*)gipk)[lane];
    st_h4(g_Kh + ((size_t)hh * LTOT + LIMG + l) * HD + lane * 4,
          xv.x*inv*gv.x, xv.y*inv*gv.y, xv.z*inv*gv.z, xv.w*inv*gv.w);
}

// ================= stage 4b: V transpose fp16 -> fp16 [h][d][key] ===========
__global__ void vt_kernel() {
    float* sm = (float*)dynsm;
    int t = blockIdx.x, hh = blockIdx.y, tid = threadIdx.x;
    const __half* vsrc = g_Vh + ((size_t)hh * LTOT + (size_t)t * 128) * HD;
    for (int i = tid; i < 128 * 16; i += 256) {
        int kr = i >> 4, c8 = i & 15;
        uint4 u = *(const uint4*)(vsrc + (size_t)kr * HD + c8 * 8);
        const __half* hp = (const __half*)&u;
        float* dst = sm + kr * 133 + c8 * 8;
#pragma unroll
        for (int e = 0; e < 8; e++) dst[e] = __half2float(hp[e]);
    }
    __syncthreads();
    for (int j = 0; j < 8; j++) {
        int g = tid + j * 256;
        int d = g >> 4, kc = g & 15;
        float f[8];
#pragma unroll
        for (int i = 0; i < 8; i++) f[i] = sm[(kc * 8 + i) * 133 + d];
        uint4 u = { pkh(f[0], f[1]), pkh(f[2], f[3]), pkh(f[4], f[5]), pkh(f[6], f[7]) };
        *reinterpret_cast<uint4*>(g_Vth + ((size_t)hh * HD + d) * LTOT + (size_t)t * 128 + kc * 8) = u;
    }
}

// ================= stage 5: flash attention, Br=128, 4 warps, split-K x2 ====
#define SQ_OFF  0
#define SK_OFF  34816
#define SK_BUF  17408
#define SV_OFF  (34816 + 2 * 17408)     // 69632
#define SV_BUF  18432
#define ATTN_SMEM (SV_OFF + 2 * SV_BUF) // 106496

__global__ void __launch_bounds__(128, 2) attn_kernel() {
    char* smem = dynsm;
    const uint32_t sb = s2u(smem);
    const int tid = threadIdx.x;
    const int w = tid >> 5, t = tid & 31;
    const int r4 = t >> 2, q4 = t & 3;
    const int hh = blockIdx.y, q0 = blockIdx.x * 128, z = blockIdx.z;
    const int k0 = z * (LTOT / 2);

    const int rowselA = t & 15;
    const int winA = (t >> 4) << 4;
    const int rowselB = (t & 7) + ((t & 16) >> 1);
    const int winB = (t & 8) << 1;

    const uint4* qg = (const uint4*)(g_Qh + ((size_t)hh * LIMG + q0) * HD);
    for (int i = tid; i < 2048; i += 128) {
        int rr = i >> 4, cc = i & 15;
        *(uint4*)(smem + SQ_OFF + rr * 272 + cc * 16) = qg[i];
    }

    const __half* kgb = g_Kh + ((size_t)hh * LTOT + k0) * HD;
    const __half* vgb = g_Vth + (size_t)hh * HD * LTOT;
#pragma unroll
    for (int pb = 0; pb < 2; pb++) {
        for (int n = 0; n < 8; n++) {
            int i = tid + n * 128;
            int kr = i >> 4, c = i & 15;
            cp16(sb + SK_OFF + pb * SK_BUF + kr * 272 + c * 16,
                 kgb + ((size_t)(pb * KT + kr)) * HD + c * 8);
            int d = i >> 3, c2 = i & 7;
            cp16(sb + SV_OFF + pb * SV_BUF + d * 144 + c2 * 16,
                 vgb + (size_t)d * LTOT + k0 + pb * KT + c2 * 8);
        }
        asm volatile("cp.async.commit_group;");
    }
    __syncthreads();

    float m[2][2] = {{-1e30f, -1e30f}, {-1e30f, -1e30f}};
    float oc[2][16][4];
#pragma unroll
    for (int mb = 0; mb < 2; mb++)
#pragma unroll
        for (int nb = 0; nb < 16; nb++)
#pragma unroll
            for (int j = 0; j < 4; j++) oc[mb][nb][j] = 0.f;
    float lacc[2][4] = {};

    const uint32_t Qb = sb + SQ_OFF;

    for (int it = 0; it < NIT2; it++) {
        const int b = it & 1;
        asm volatile("cp.async.wait_group 1;");
        __syncthreads();

        float sc[2][8][4];
#pragma unroll
        for (int mb = 0; mb < 2; mb++)
#pragma unroll
            for (int nb = 0; nb < 8; nb++)
#pragma unroll
                for (int j = 0; j < 4; j++) sc[mb][nb][j] = 0.f;
        const uint32_t Kb = sb + SK_OFF + b * SK_BUF;
#pragma unroll
        for (int kb = 0; kb < 8; kb++) {
            uint32_t qa0[4], qa1[4];
            ldsm4(qa0, Qb + (w * 32 + rowselA) * 272 + kb * 32 + winA);
            ldsm4(qa1, Qb + (w * 32 + 16 + rowselA) * 272 + kb * 32 + winA);
#pragma unroll
            for (int nb2 = 0; nb2 < 4; nb2++) {
                uint32_t bb[4];
                ldsm4(bb, Kb + (nb2 * 16 + rowselB) * 272 + kb * 32 + winB);
                mma_f16(sc[0][2 * nb2],     qa0, bb[0], bb[1]);
                mma_f16(sc[0][2 * nb2 + 1], qa0, bb[2], bb[3]);
                mma_f16(sc[1][2 * nb2],     qa1, bb[0], bb[1]);
                mma_f16(sc[1][2 * nb2 + 1], qa1, bb[2], bb[3]);
            }
        }

        float mn[2][2];
#pragma unroll
        for (int mb = 0; mb < 2; mb++) {
            float mt_lo = -1e30f, mt_hi = -1e30f;
#pragma unroll
            for (int n = 0; n < 8; n++) {
                mt_lo = fmaxf(mt_lo, fmaxf(sc[mb][n][0], sc[mb][n][1]));
                mt_hi = fmaxf(mt_hi, fmaxf(sc[mb][n][2], sc[mb][n][3]));
            }
            mt_lo = fmaxf(mt_lo, __shfl_xor_sync(0xffffffffu, mt_lo, 1));
            mt_lo = fmaxf(mt_lo, __shfl_xor_sync(0xffffffffu, mt_lo, 2));
            mt_hi = fmaxf(mt_hi, __shfl_xor_sync(0xffffffffu, mt_hi, 1));
            mt_hi = fmaxf(mt_hi, __shfl_xor_sync(0xffffffffu, mt_hi, 2));
            mn[mb][0] = fmaxf(m[mb][0], mt_lo);
            mn[mb][1] = fmaxf(m[mb][1], mt_hi);
        }
        bool upd = (mn[0][0] > m[0][0]) | (mn[0][1] > m[0][1]) |
                   (mn[1][0] > m[1][0]) | (mn[1][1] > m[1][1]);
        if (__any_sync(0xffffffffu, upd)) {
#pragma unroll
            for (int mb = 0; mb < 2; mb++) {
                float co_lo = ex2(m[mb][0] - mn[mb][0]);
                float co_hi = ex2(m[mb][1] - mn[mb][1]);
#pragma unroll
                for (int nb = 0; nb < 16; nb++) {
                    oc[mb][nb][0] *= co_lo; oc[mb][nb][1] *= co_lo;
                    oc[mb][nb][2] *= co_hi; oc[mb][nb][3] *= co_hi;
                }
                lacc[mb][0] *= co_lo; lacc[mb][1] *= co_lo;
                lacc[mb][2] *= co_hi; lacc[mb][3] *= co_hi;
            }
        }
#pragma unroll
        for (int mb = 0; mb < 2; mb++) { m[mb][0] = mn[mb][0]; m[mb][1] = mn[mb][1]; }

        const uint32_t Vb = sb + SV_OFF + b * SV_BUF;
#pragma unroll
        for (int kbg = 0; kbg < 4; kbg++) {
            uint32_t pa0[4], pa1[4];
            pa0[0] = hex2(pk2(sc[0][2*kbg][0]   - m[0][0], sc[0][2*kbg][1]   - m[0][0]));
            pa0[1] = hex2(pk2(sc[0][2*kbg][2]   - m[0][1], sc[0][2*kbg][3]   - m[0][1]));
            pa0[2] = hex2(pk2(sc[0][2*kbg+1][0] - m[0][0], sc[0][2*kbg+1][1] - m[0][0]));
            pa0[3] = hex2(pk2(sc[0][2*kbg+1][2] - m[0][1], sc[0][2*kbg+1][3] - m[0][1]));
            pa1[0] = hex2(pk2(sc[1][2*kbg][0]   - m[1][0], sc[1][2*kbg][1]   - m[1][0]));
            pa1[1] = hex2(pk2(sc[1][2*kbg][2]   - m[1][1], sc[1][2*kbg][3]   - m[1][1]));
            pa1[2] = hex2(pk2(sc[1][2*kbg+1][0] - m[1][0], sc[1][2*kbg+1][1] - m[1][0]));
            pa1[3] = hex2(pk2(sc[1][2*kbg+1][2] - m[1][1], sc[1][2*kbg+1][3] - m[1][1]));

            mma_f16(lacc[0], pa0, ONES2, ONES2);
            mma_f16(lacc[1], pa1, ONES2, ONES2);

#pragma unroll
            for (int nb2 = 0; nb2 < 8; nb2++) {
                uint32_t bb[4];
                ldsm4(bb, Vb + (nb2 * 16 + rowselB) * 144 + kbg * 32 + winB);
                mma_f16(oc[0][2 * nb2],     pa0, bb[0], bb[1]);
                mma_f16(oc[0][2 * nb2 + 1], pa0, bb[2], bb[3]);
                mma_f16(oc[1][2 * nb2],     pa1, bb[0], bb[1]);
                mma_f16(oc[1][2 * nb2 + 1], pa1, bb[2], bb[3]);
            }
        }
        __syncthreads();

        if (it + 2 < NIT2) {
            for (int n = 0; n < 8; n++) {
                int i = tid + n * 128;
                int kr = i >> 4, c = i & 15;
                cp16(sb + SK_OFF + b * SK_BUF + kr * 272 + c * 16,
                     kgb + ((size_t)((it + 2) * KT + kr)) * HD + c * 8);
                int d = i >> 3, c2 = i & 7;
                cp16(sb + SV_OFF + b * SV_BUF + d * 144 + c2 * 16,
                     vgb + (size_t)d * LTOT + k0 + (it + 2) * KT + c2 * 8);
            }
        }
        asm volatile("cp.async.commit_group;");
    }

    // ---- epilogue: fp16 unnormalized partials + (m, l) ----
    __half* ob = g_Oparth[z] + ((size_t)hh * LIMG + q0) * HD;
#pragma unroll
    for (int mb = 0; mb < 2; mb++) {
        __half* orow_lo = ob + (size_t)(w * 32 + mb * 16 + r4) * HD + 2 * q4;
        __half* orow_hi = orow_lo + 8 * HD;
#pragma unroll
        for (int nb = 0; nb < 16; nb++) {
            *(uint32_t*)(orow_lo + nb * 8) = pkh(oc[mb][nb][0], oc[mb][nb][1]);
            *(uint32_t*)(orow_hi + nb * 8) = pkh(oc[mb][nb][2], oc[mb][nb][3]);
        }
        if (q4 == 0) {
            size_t row = (size_t)hh * LIMG + q0 + w * 32 + mb * 16 + r4;
            g_ML[z][row * 2]           = m[mb][0];
            g_ML[z][row * 2 + 1]       = lacc[mb][0];
            g_ML[z][(row + 8) * 2]     = m[mb][1];
            g_ML[z][(row + 8) * 2 + 1] = lacc[mb][2];
        }
    }
}

// ================= stage 6: split-K combine (fp16 partials) ==================
__global__ void attn_reduce_kernel(float* __restrict__ out) {
    size_t gidx = (size_t)blockIdx.x * 256 + threadIdx.x;  // one 8-col chunk each
    size_t row = gidx >> 4;               // HD/8 = 16 chunks per row
    int chunk = (int)(gidx & 15);
    int hh = (int)(row / LIMG), q = (int)(row % LIMG);
    float m0 = g_ML[0][row * 2], l0 = g_ML[0][row * 2 + 1];
    float m1 = g_ML[1][row * 2], l1 = g_ML[1][row * 2 + 1];
    float ms = fmaxf(m0, m1);
    float c0 = ex2(m0 - ms), c1 = ex2(m1 - ms);
    float inv = 1.f / (l0 * c0 + l1 * c1);
    uint4 u0 = *(const uint4*)(g_Oparth[0] + row * HD + chunk * 8);
    uint4 u1 = *(const uint4*)(g_Oparth[1] + row * HD + chunk * 8);
    const __half* h0 = (const __half*)&u0;
    const __half* h1 = (const __half*)&u1;
    float* op = out + (size_t)q * DMOD + hh * HD + chunk * 8;
    float4 r0, r1;
    r0.x = (__half2float(h0[0]) * c0 + __half2float(h1[0]) * c1) * inv;
    r0.y = (__half2float(h0[1]) * c0 + __half2float(h1[1]) * c1) * inv;
    r0.z = (__half2float(h0[2]) * c0 + __half2float(h1[2]) * c1) * inv;
    r0.w = (__half2float(h0[3]) * c0 + __half2float(h1[3]) * c1) * inv;
    r1.x = (__half2float(h0[4]) * c0 + __half2float(h1[4]) * c1) * inv;
    r1.y = (__half2float(h0[5]) * c0 + __half2float(h1[5]) * c1) * inv;
    r1.z = (__half2float(h0[6]) * c0 + __half2float(h1[6]) * c1) * inv;
    r1.w = (__half2float(h0[7]) * c0 + __half2float(h1[7]) * c1) * inv;
    *(float4*)(op)     = r0;
    *(float4*)(op + 4) = r1;
}

// ================= launch =====================================================
extern "C" void kernel_launch(void* const* d_in, const int* in_sizes, int n_in,
                              void* d_out, int out_size) {
    const float* ip   = (const float*)d_in[0];
    const float* q    = (const float*)d_in[1];
    const float* k    = (const float*)d_in[2];
    const float* v    = (const float*)d_in[3];
    const float* temb = (const float*)d_in[4];
    const float* wada = (const float*)d_in[5];
    const float* bada = (const float*)d_in[6];
    const float* wk   = (const float*)d_in[7];
    const float* wv   = (const float*)d_in[8];
    const float* gq   = (const float*)d_in[9];
    const float* gk   = (const float*)d_in[10];
    const float* gipk = (const float*)d_in[11];
    float* out = (float*)d_out;

    ada_kernel<<<(2 * DIP + 7) / 8, 256>>>(temb, wada, bada);
    adaln_kernel<<<LIP, 256>>>(ip);
    wconv_kernel<<<dim3(DMOD * DIP / 1024, 2), 256>>>(wk, wv);

    cudaFuncSetAttribute(ip_gemm_h_kernel, cudaFuncAttributeMaxDynamicSharedMemorySize, GEMM_SMEM);
    ip_gemm_h_kernel<<<dim3(DMOD * 2 / 192, LIP / 128), 256, GEMM_SMEM>>>();

    qkv_rms_kernel<<<(LIMG * H + 7) / 8, 256>>>(q, k, v, gq, gk);
    ipk_rms_kernel<<<(LIP * H + 7) / 8, 256>>>(gipk);

    cudaFuncSetAttribute(vt_kernel, cudaFuncAttributeMaxDynamicSharedMemorySize, 128 * 133 * 4);
    vt_kernel<<<dim3(LTOT / 128, H), 256, 128 * 133 * 4>>>();

    cudaFuncSetAttribute(attn_kernel, cudaFuncAttributeMaxDynamicSharedMemorySize, ATTN_SMEM);
    attn_kernel<<<dim3(LIMG / 128, H, 2), 128, ATTN_SMEM>>>();

    attn_reduce_kernel<<<(H * LIMG * HD / 8) / 256, 256>>>(out);
}

// round 16
// speedup vs baseline: 1.0635x; 1.0635x over previous
#include <cuda_runtime.h>
#include <cuda_fp16.h>
#include <math.h>
#include <stdint.h>

#define H     24
#define LIMG  2048
#define LIP   512
#define DMOD  3072
#define DIP   1280
#define HD    128
#define LTOT  2560
#define KT    64
#define NIT2  20                // key tiles per split (LTOT/2/KT)
#define SCALE2 0.1275174735772347f
#define ONES2 0x3C003C00u

// ================= scratch =================
__device__ float  g_e[2 * DIP];
__device__ __half g_ipnorm_h[LIP * DIP];
__device__ __half g_Wh[2 * (size_t)DMOD * DIP];
__device__ float  g_ipk_raw[LIP * DMOD];
__device__ __half g_Vh[(size_t)H * LTOT * HD];         // fp16 [h][key][d] (K-layout)
__device__ __half g_Qh[(size_t)H * LIMG * HD];
__device__ __half g_Kh[(size_t)H * LTOT * HD];
__device__ float  g_Opart[2][(size_t)H * LIMG * HD];   // split-K partial O (fp32)
__device__ float  g_ML[2][(size_t)H * LIMG * 2];       // per-row (m, l)

__device__ __forceinline__ uint32_t s2u(const void* p) {
    uint32_t a;
    asm("{ .reg .u64 t; cvta.to.shared.u64 t, %1; cvt.u32.u64 %0, t; }" : "=r"(a) : "l"(p));
    return a;
}
__device__ __forceinline__ uint32_t pkh(float a, float b) {
    __half2 h = __floats2half2_rn(a, b);
    return *reinterpret_cast<uint32_t*>(&h);
}
__device__ __forceinline__ uint32_t pk2(float lo, float hi) {
    uint32_t d;
    asm("cvt.rn.f16x2.f32 %0, %1, %2;" : "=r"(d) : "f"(hi), "f"(lo));
    return d;
}
__device__ __forceinline__ uint32_t hex2(uint32_t x) {
    uint32_t d;
    asm("ex2.approx.f16x2 %0, %1;" : "=r"(d) : "r"(x));
    return d;
}
__device__ __forceinline__ float ex2(float x) {
    float y;
    asm("ex2.approx.f32 %0, %1;" : "=f"(y) : "f"(x));
    return y;
}
__device__ __forceinline__ void mma_f16(float* c, const uint32_t* a, uint32_t b0, uint32_t b1) {
    asm volatile("mma.sync.aligned.m16n8k16.row.col.f32.f16.f16.f32 "
        "{%0,%1,%2,%3}, {%4,%5,%6,%7}, {%8,%9}, {%0,%1,%2,%3};"
        : "+f"(c[0]), "+f"(c[1]), "+f"(c[2]), "+f"(c[3])
        : "r"(a[0]), "r"(a[1]), "r"(a[2]), "r"(a[3]), "r"(b0), "r"(b1));
}
__device__ __forceinline__ void ldsm4(uint32_t* r, uint32_t addr) {
    asm volatile("ldmatrix.sync.aligned.m8n8.x4.shared.b16 {%0,%1,%2,%3}, [%4];"
        : "=r"(r[0]), "=r"(r[1]), "=r"(r[2]), "=r"(r[3]) : "r"(addr));
}
__device__ __forceinline__ void ldsm4t(uint32_t* r, uint32_t addr) {
    asm volatile("ldmatrix.sync.aligned.m8n8.x4.trans.shared.b16 {%0,%1,%2,%3}, [%4];"
        : "=r"(r[0]), "=r"(r[1]), "=r"(r[2]), "=r"(r[3]) : "r"(addr));
}
__device__ __forceinline__ void cp16(uint32_t dst, const void* src) {
    asm volatile("cp.async.cg.shared.global [%0], [%1], 16;" :: "r"(dst), "l"(src));
}

extern __shared__ __align__(16) char dynsm[];

// ================= stage 1: ada ================
__global__ void ada_kernel(const float* __restrict__ t_emb,
                           const float* __restrict__ w_ada,
                           const float* __restrict__ b_ada) {
    int o = blockIdx.x * 8 + (threadIdx.x >> 5);
    int lane = threadIdx.x & 31;
    if (o >= 2 * DIP) return;
    const float* w = w_ada + (size_t)o * DIP;
    float s = 0.f;
    for (int i = lane; i < DIP; i += 32) {
        float t = t_emb[i];
        s += (t / (1.f + expf(-t))) * w[i];
    }
#pragma unroll
    for (int off = 16; off; off >>= 1) s += __shfl_xor_sync(0xffffffffu, s, off);
    if (lane == 0) g_e[o] = s + b_ada[o];
}

// ================= stage 2: AdaLN -> fp16 ================
__global__ void adaln_kernel(const float* __restrict__ ip) {
    int row = blockIdx.x;
    const float* x = ip + (size_t)row * DIP;
    __shared__ float red1[8], red2[8];
    float s = 0.f, s2 = 0.f;
    for (int i = threadIdx.x; i < DIP; i += 256) {
        float v = x[i]; s += v; s2 += v * v;
    }
#pragma unroll
    for (int off = 16; off; off >>= 1) {
        s  += __shfl_xor_sync(0xffffffffu, s, off);
        s2 += __shfl_xor_sync(0xffffffffu, s2, off);
    }
    int w = threadIdx.x >> 5, lane = threadIdx.x & 31;
    if (lane == 0) { red1[w] = s; red2[w] = s2; }
    __syncthreads();
    float ts = 0.f, ts2 = 0.f;
#pragma unroll
    for (int i = 0; i < 8; i++) { ts += red1[i]; ts2 += red2[i]; }
    float mu = ts / DIP;
    float inv = rsqrtf(ts2 / DIP - mu * mu + 1e-6f);
    for (int i = threadIdx.x; i < DIP; i += 256) {
        float xn = (x[i] - mu) * inv;
        g_ipnorm_h[(size_t)row * DIP + i] = __float2half(xn * (1.f + g_e[DIP + i]) + g_e[i]);
    }
}

// ================= stage 2b: weight fp32 -> fp16 ================
__global__ void wconv_kernel(const float* __restrict__ wk, const float* __restrict__ wv) {
    size_t i = ((size_t)blockIdx.x * 256 + threadIdx.x) * 4;
    const float* src = blockIdx.y ? wv : wk;
    __half* dst = g_Wh + (size_t)blockIdx.y * DMOD * DIP;
    float4 f = *(const float4*)(src + i);
    uint2 u = { pkh(f.x, f.y), pkh(f.z, f.w) };
    *(uint2*)(dst + i) = u;
}

// ================= stage 3: fused ip GEMM, 2x4 warp grid =====================
#define GEMM_SMEM 92160

__device__ __forceinline__ void gemm_issue(uint32_t sb, int tid, int bm, int bn,
                                           int ks, int buf) {
#pragma unroll
    for (int n = 0; n < 4; n++) {
        int i = tid + n * 256;
        int row = i >> 3, c = i & 7;
        cp16(sb + buf * 18432 + row * 144 + c * 16,
             g_ipnorm_h + (size_t)(bm + row) * DIP + ks * 64 + c * 8);
    }
#pragma unroll
    for (int n = 0; n < 6; n++) {
        int i = tid + n * 256;
        int row = i >> 3, c = i & 7;
        cp16(sb + 36864 + buf * 27648 + row * 144 + c * 16,
             g_Wh + (size_t)(bn + row) * DIP + ks * 64 + c * 8);
    }
    asm volatile("cp.async.commit_group;");
}

__global__ void __launch_bounds__(256, 1) ip_gemm_h_kernel() {
    const uint32_t sb = s2u(dynsm);
    const int tid = threadIdx.x;
    const int w = tid >> 5, t = tid & 31;
    const int r4 = t >> 2, q4 = t & 3;
    const int wr = w >> 2, wc = w & 3;
    const int bn = blockIdx.x * 192, bm = blockIdx.y * 128;

    gemm_issue(sb, tid, bm, bn, 0, 0);
    gemm_issue(sb, tid, bm, bn, 1, 1);

    float oc[4][6][4] = {};
    const int rowselA = t & 15;
    const int winA = (t >> 4) << 4;
    const int rowselB = (t & 7) + ((t & 16) >> 1);
    const int winB = (t & 8) << 1;

    for (int ks = 0; ks < 20; ks++) {
        const int buf = ks & 1;
        if (ks < 18) asm volatile("cp.async.wait_group 1;");
        else         asm volatile("cp.async.wait_group 0;");
        __syncthreads();
        const uint32_t Ab = sb + buf * 18432;
        const uint32_t Bb = sb + 36864 + buf * 27648;
#pragma unroll
        for (int kb = 0; kb < 4; kb++) {
            uint32_t aa[4][4];
#pragma unroll
            for (int mb = 0; mb < 4; mb++)
                ldsm4(aa[mb], Ab + (wr * 64 + mb * 16 + rowselA) * 144 + kb * 32 + winA);
#pragma unroll
            for (int nb = 0; nb < 3; nb++) {
                uint32_t bb[4];
                ldsm4(bb, Bb + (wc * 48 + nb * 16 + rowselB) * 144 + kb * 32 + winB);
#pragma unroll
                for (int mb = 0; mb < 4; mb++) {
                    mma_f16(oc[mb][2 * nb],     aa[mb], bb[0], bb[1]);
                    mma_f16(oc[mb][2 * nb + 1], aa[mb], bb[2], bb[3]);
                }
            }
        }
        __syncthreads();
        if (ks + 2 < 20) gemm_issue(sb, tid, bm, bn, ks + 2, buf);
        else asm volatile("cp.async.commit_group;");
    }

#pragma unroll
    for (int mb = 0; mb < 4; mb++) {
        const int m_lo = bm + wr * 64 + mb * 16 + r4, m_hi = m_lo + 8;
#pragma unroll
        for (int nbp = 0; nbp < 6; nbp++) {
            int n = bn + wc * 48 + nbp * 8 + q4 * 2;
            if (n < DMOD) {
                float2 vlo = { oc[mb][nbp][0], oc[mb][nbp][1] };
                float2 vhi = { oc[mb][nbp][2], oc[mb][nbp][3] };
                *(float2*)(g_ipk_raw + (size_t)m_lo * DMOD + n) = vlo;
                *(float2*)(g_ipk_raw + (size_t)m_hi * DMOD + n) = vhi;
            } else {
                int nn = n - DMOD;
                int hh = nn >> 7, dd = nn & 127;
                *(uint32_t*)(g_Vh + ((size_t)hh * LTOT + LIMG + m_lo) * HD + dd) =
                    pkh(oc[mb][nbp][0], oc[mb][nbp][1]);
                *(uint32_t*)(g_Vh + ((size_t)hh * LTOT + LIMG + m_hi) * HD + dd) =
                    pkh(oc[mb][nbp][2], oc[mb][nbp][3]);
            }
        }
    }
}

// ================= stage 4: RMS + fp16 pack ================
__device__ __forceinline__ float warp_sum(float s) {
#pragma unroll
    for (int off = 16; off; off >>= 1) s += __shfl_xor_sync(0xffffffffu, s, off);
    return s;
}
__device__ __forceinline__ void st_h4(__half* p, float a, float b, float c, float d) {
    uint2 u = { pkh(a, b), pkh(c, d) };
    *reinterpret_cast<uint2*>(p) = u;
}

__global__ void qkv_rms_kernel(const float* __restrict__ q,
                               const float* __restrict__ k,
                               const float* __restrict__ v,
                               const float* __restrict__ gq,
                               const float* __restrict__ gk) {
    int rid = blockIdx.x * 8 + (threadIdx.x >> 5);
    if (rid >= LIMG * H) return;
    int lane = threadIdx.x & 31;
    int l = rid / H, hh = rid % H;
    size_t src = (size_t)l * DMOD + hh * HD + lane * 4;

    float4 xv = *(const float4*)(q + src);
    float inv = rsqrtf(warp_sum(xv.x*xv.x + xv.y*xv.y + xv.z*xv.z + xv.w*xv.w) / 128.f + 1e-6f) * SCALE2;
    float4 gv = ((const float4*)gq)[lane];
    st_h4(g_Qh + ((size_t)hh * LIMG + l) * HD + lane * 4,
          xv.x*inv*gv.x, xv.y*inv*gv.y, xv.z*inv*gv.z, xv.w*inv*gv.w);

    xv = *(const float4*)(k + src);
    inv = rsqrtf(warp_sum(xv.x*xv.x + xv.y*xv.y + xv.z*xv.z + xv.w*xv.w) / 128.f + 1e-6f);
    gv = ((const float4*)gk)[lane];
    st_h4(g_Kh + ((size_t)hh * LTOT + l) * HD + lane * 4,
          xv.x*inv*gv.x, xv.y*inv*gv.y, xv.z*inv*gv.z, xv.w*inv*gv.w);

    xv = *(const float4*)(v + src);
    st_h4(g_Vh + ((size_t)hh * LTOT + l) * HD + lane * 4, xv.x, xv.y, xv.z, xv.w);
}

__global__ void ipk_rms_kernel(const float* __restrict__ gipk) {
    int rid = blockIdx.x * 8 + (threadIdx.x >> 5);
    if (rid >= LIP * H) return;
    int lane = threadIdx.x & 31;
    int l = rid / H, hh = rid % H;
    float4 xv = *(const float4*)(g_ipk_raw + (size_t)l * DMOD + hh * HD + lane * 4);
    float inv = rsqrtf(warp_sum(xv.x*xv.x + xv.y*xv.y + xv.z*xv.z + xv.w*xv.w) / 128.f + 1e-6f);
    float4 gv = ((const float4*)gipk)[lane];
    st_h4(g_Kh + ((size_t)hh * LTOT + LIMG + l) * HD + lane * 4,
          xv.x*inv*gv.x, xv.y*inv*gv.y, xv.z*inv*gv.z, xv.w*inv*gv.w);
}

// ================= stage 5: flash attention, Br=128, split-K x2 ==============
// V loaded key-major (same layout as K) and fed to PV via ldmatrix.trans.
// SMEM: Q 128x272B | K 2x(64x272B) | V 2x(64x272B) = 104448 B (2 CTA/SM)
#define SQ_OFF  0
#define SK_OFF  34816
#define SK_BUF  17408
#define SV_OFF  (34816 + 2 * 17408)     // 69632
#define SV_BUF  17408
#define ATTN_SMEM (SV_OFF + 2 * SV_BUF) // 104448

__global__ void __launch_bounds__(128, 2) attn_kernel() {
    char* smem = dynsm;
    const uint32_t sb = s2u(smem);
    const int tid = threadIdx.x;
    const int w = tid >> 5, t = tid & 31;
    const int r4 = t >> 2, q4 = t & 3;
    const int hh = blockIdx.y, q0 = blockIdx.x * 128, z = blockIdx.z;
    const int k0 = z * (LTOT / 2);

    const int rowselA = t & 15;
    const int winA = (t >> 4) << 4;
    const int rowselB = (t & 7) + ((t & 16) >> 1);
    const int winB = (t & 8) << 1;
    // trans B-frag addressing (V from key-major rows)
    const int rowV = (t & 7) + (t & 8);     // +8 for lanes 8-15, 24-31
    const int colV = (t & 16);              // +16B for lanes 16-31

    const uint4* qg = (const uint4*)(g_Qh + ((size_t)hh * LIMG + q0) * HD);
    for (int i = tid; i < 2048; i += 128) {
        int rr = i >> 4, cc = i & 15;
        *(uint4*)(smem + SQ_OFF + rr * 272 + cc * 16) = qg[i];
    }

    const __half* kgb = g_Kh + ((size_t)hh * LTOT + k0) * HD;
    const __half* vgb = g_Vh + ((size_t)hh * LTOT + k0) * HD;
#pragma unroll
    for (int pb = 0; pb < 2; pb++) {
        for (int n = 0; n < 8; n++) {
            int i = tid + n * 128;
            int kr = i >> 4, c = i & 15;
            cp16(sb + SK_OFF + pb * SK_BUF + kr * 272 + c * 16,
                 kgb + ((size_t)(pb * KT + kr)) * HD + c * 8);
            cp16(sb + SV_OFF + pb * SV_BUF + kr * 272 + c * 16,
                 vgb + ((size_t)(pb * KT + kr)) * HD + c * 8);
        }
        asm volatile("cp.async.commit_group;");
    }
    __syncthreads();

    float m[2][2] = {{-1e30f, -1e30f}, {-1e30f, -1e30f}};
    float oc[2][16][4];
#pragma unroll
    for (int mb = 0; mb < 2; mb++)
#pragma unroll
        for (int nb = 0; nb < 16; nb++)
#pragma unroll
            for (int j = 0; j < 4; j++) oc[mb][nb][j] = 0.f;
    float lacc[2][4] = {};

    const uint32_t Qb = sb + SQ_OFF;

    for (int it = 0; it < NIT2; it++) {
        const int b = it & 1;
        asm volatile("cp.async.wait_group 1;");
        __syncthreads();

        float sc[2][8][4];
#pragma unroll
        for (int mb = 0; mb < 2; mb++)
#pragma unroll
            for (int nb = 0; nb < 8; nb++)
#pragma unroll
                for (int j = 0; j < 4; j++) sc[mb][nb][j] = 0.f;
        const uint32_t Kb = sb + SK_OFF + b * SK_BUF;
#pragma unroll
        for (int kb = 0; kb < 8; kb++) {
            uint32_t qa0[4], qa1[4];
            ldsm4(qa0, Qb + (w * 32 + rowselA) * 272 + kb * 32 + winA);
            ldsm4(qa1, Qb + (w * 32 + 16 + rowselA) * 272 + kb * 32 + winA);
#pragma unroll
            for (int nb2 = 0; nb2 < 4; nb2++) {
                uint32_t bb[4];
                ldsm4(bb, Kb + (nb2 * 16 + rowselB) * 272 + kb * 32 + winB);
                mma_f16(sc[0][2 * nb2],     qa0, bb[0], bb[1]);
                mma_f16(sc[0][2 * nb2 + 1], qa0, bb[2], bb[3]);
                mma_f16(sc[1][2 * nb2],     qa1, bb[0], bb[1]);
                mma_f16(sc[1][2 * nb2 + 1], qa1, bb[2], bb[3]);
            }
        }

        float mn[2][2];
#pragma unroll
        for (int mb = 0; mb < 2; mb++) {
            float mt_lo = -1e30f, mt_hi = -1e30f;
#pragma unroll
            for (int n = 0; n < 8; n++) {
                mt_lo = fmaxf(mt_lo, fmaxf(sc[mb][n][0], sc[mb][n][1]));
                mt_hi = fmaxf(mt_hi, fmaxf(sc[mb][n][2], sc[mb][n][3]));
            }
            mt_lo = fmaxf(mt_lo, __shfl_xor_sync(0xffffffffu, mt_lo, 1));
            mt_lo = fmaxf(mt_lo, __shfl_xor_sync(0xffffffffu, mt_lo, 2));
            mt_hi = fmaxf(mt_hi, __shfl_xor_sync(0xffffffffu, mt_hi, 1));
            mt_hi = fmaxf(mt_hi, __shfl_xor_sync(0xffffffffu, mt_hi, 2));
            mn[mb][0] = fmaxf(m[mb][0], mt_lo);
            mn[mb][1] = fmaxf(m[mb][1], mt_hi);
        }
        bool upd = (mn[0][0] > m[0][0]) | (mn[0][1] > m[0][1]) |
                   (mn[1][0] > m[1][0]) | (mn[1][1] > m[1][1]);
        if (__any_sync(0xffffffffu, upd)) {
#pragma unroll
            for (int mb = 0; mb < 2; mb++) {
                float co_lo = ex2(m[mb][0] - mn[mb][0]);
                float co_hi = ex2(m[mb][1] - mn[mb][1]);
#pragma unroll
                for (int nb = 0; nb < 16; nb++) {
                    oc[mb][nb][0] *= co_lo; oc[mb][nb][1] *= co_lo;
                    oc[mb][nb][2] *= co_hi; oc[mb][nb][3] *= co_hi;
                }
                lacc[mb][0] *= co_lo; lacc[mb][1] *= co_lo;
                lacc[mb][2] *= co_hi; lacc[mb][3] *= co_hi;
            }
        }
#pragma unroll
        for (int mb = 0; mb < 2; mb++) { m[mb][0] = mn[mb][0]; m[mb][1] = mn[mb][1]; }

        const uint32_t Vb = sb + SV_OFF + b * SV_BUF;
#pragma unroll
        for (int kbg = 0; kbg < 4; kbg++) {
            uint32_t pa0[4], pa1[4];
            pa0[0] = hex2(pk2(sc[0][2*kbg][0]   - m[0][0], sc[0][2*kbg][1]   - m[0][0]));
            pa0[1] = hex2(pk2(sc[0][2*kbg][2]   - m[0][1], sc[0][2*kbg][3]   - m[0][1]));
            pa0[2] = hex2(pk2(sc[0][2*kbg+1][0] - m[0][0], sc[0][2*kbg+1][1] - m[0][0]));
            pa0[3] = hex2(pk2(sc[0][2*kbg+1][2] - m[0][1], sc[0][2*kbg+1][3] - m[0][1]));
            pa1[0] = hex2(pk2(sc[1][2*kbg][0]   - m[1][0], sc[1][2*kbg][1]   - m[1][0]));
            pa1[1] = hex2(pk2(sc[1][2*kbg][2]   - m[1][1], sc[1][2*kbg][3]   - m[1][1]));
            pa1[2] = hex2(pk2(sc[1][2*kbg+1][0] - m[1][0], sc[1][2*kbg+1][1] - m[1][0]));
            pa1[3] = hex2(pk2(sc[1][2*kbg+1][2] - m[1][1], sc[1][2*kbg+1][3] - m[1][1]));

            mma_f16(lacc[0], pa0, ONES2, ONES2);
            mma_f16(lacc[1], pa1, ONES2, ONES2);

#pragma unroll
            for (int nb2 = 0; nb2 < 8; nb2++) {
                uint32_t bb[4];
                ldsm4t(bb, Vb + (kbg * 16 + rowV) * 272 + nb2 * 32 + colV);
                mma_f16(oc[0][2 * nb2],     pa0, bb[0], bb[1]);
                mma_f16(oc[0][2 * nb2 + 1], pa0, bb[2], bb[3]);
                mma_f16(oc[1][2 * nb2],     pa1, bb[0], bb[1]);
                mma_f16(oc[1][2 * nb2 + 1], pa1, bb[2], bb[3]);
            }
        }
        __syncthreads();

        if (it + 2 < NIT2) {
            for (int n = 0; n < 8; n++) {
                int i = tid + n * 128;
                int kr = i >> 4, c = i & 15;
                cp16(sb + SK_OFF + b * SK_BUF + kr * 272 + c * 16,
                     kgb + ((size_t)((it + 2) * KT + kr)) * HD + c * 8);
                cp16(sb + SV_OFF + b * SV_BUF + kr * 272 + c * 16,
                     vgb + ((size_t)((it + 2) * KT + kr)) * HD + c * 8);
            }
        }
        asm volatile("cp.async.commit_group;");
    }

    // ---- epilogue: fp32 unnormalized partials + (m, l) ----
    float* ob = g_Opart[z] + ((size_t)hh * LIMG + q0) * HD;
#pragma unroll
    for (int mb = 0; mb < 2; mb++) {
        float* orow_lo = ob + (size_t)(w * 32 + mb * 16 + r4) * HD + 2 * q4;
        float* orow_hi = orow_lo + 8 * HD;
#pragma unroll
        for (int nb = 0; nb < 16; nb++) {
            float2 vlo = { oc[mb][nb][0], oc[mb][nb][1] };
            float2 vhi = { oc[mb][nb][2], oc[mb][nb][3] };
            *(float2*)(orow_lo + nb * 8) = vlo;
            *(float2*)(orow_hi + nb * 8) = vhi;
        }
        if (q4 == 0) {
            size_t row = (size_t)hh * LIMG + q0 + w * 32 + mb * 16 + r4;
            g_ML[z][row * 2]           = m[mb][0];
            g_ML[z][row * 2 + 1]       = lacc[mb][0];
            g_ML[z][(row + 8) * 2]     = m[mb][1];
            g_ML[z][(row + 8) * 2 + 1] = lacc[mb][2];
        }
    }
}

// ================= stage 6: split-K combine ==================================
__global__ void attn_reduce_kernel(float* __restrict__ out) {
    size_t gidx = (size_t)blockIdx.x * 256 + threadIdx.x;  // one float4 each
    size_t row = gidx >> 5;               // HD/4 = 32 chunks per row
    int chunk = (int)(gidx & 31);
    int hh = (int)(row / LIMG), q = (int)(row % LIMG);
    float m0 = g_ML[0][row * 2], l0 = g_ML[0][row * 2 + 1];
    float m1 = g_ML[1][row * 2], l1 = g_ML[1][row * 2 + 1];
    float ms = fmaxf(m0, m1);
    float c0 = ex2(m0 - ms), c1 = ex2(m1 - ms);
    float inv = 1.f / (l0 * c0 + l1 * c1);
    float4 o0 = *(const float4*)(g_Opart[0] + row * HD + chunk * 4);
    float4 o1 = *(const float4*)(g_Opart[1] + row * HD + chunk * 4);
    float4 r = { (o0.x * c0 + o1.x * c1) * inv,
                 (o0.y * c0 + o1.y * c1) * inv,
                 (o0.z * c0 + o1.z * c1) * inv,
                 (o0.w * c0 + o1.w * c1) * inv };
    *(float4*)(out + (size_t)q * DMOD + hh * HD + chunk * 4) = r;
}

// ================= launch =====================================================
extern "C" void kernel_launch(void* const* d_in, const int* in_sizes, int n_in,
                              void* d_out, int out_size) {
    const float* ip   = (const float*)d_in[0];
    const float* q    = (const float*)d_in[1];
    const float* k    = (const float*)d_in[2];
    const float* v    = (const float*)d_in[3];
    const float* temb = (const float*)d_in[4];
    const float* wada = (const float*)d_in[5];
    const float* bada = (const float*)d_in[6];
    const float* wk   = (const float*)d_in[7];
    const float* wv   = (const float*)d_in[8];
    const float* gq   = (const float*)d_in[9];
    const float* gk   = (const float*)d_in[10];
    const float* gipk = (const float*)d_in[11];
    float* out = (float*)d_out;

    ada_kernel<<<(2 * DIP + 7) / 8, 256>>>(temb, wada, bada);
    adaln_kernel<<<LIP, 256>>>(ip);
    wconv_kernel<<<dim3(DMOD * DIP / 1024, 2), 256>>>(wk, wv);

    cudaFuncSetAttribute(ip_gemm_h_kernel, cudaFuncAttributeMaxDynamicSharedMemorySize, GEMM_SMEM);
    ip_gemm_h_kernel<<<dim3(DMOD * 2 / 192, LIP / 128), 256, GEMM_SMEM>>>();

    qkv_rms_kernel<<<(LIMG * H + 7) / 8, 256>>>(q, k, v, gq, gk);
    ipk_rms_kernel<<<(LIP * H + 7) / 8, 256>>>(gipk);

    cudaFuncSetAttribute(attn_kernel, cudaFuncAttributeMaxDynamicSharedMemorySize, ATTN_SMEM);
    attn_kernel<<<dim3(LIMG / 128, H, 2), 128, ATTN_SMEM>>>();

    attn_reduce_kernel<<<(H * LIMG * HD / 4) / 256, 256>>>(out);
}

// round 17
// speedup vs baseline: 1.0829x; 1.0183x over previous
#include <cuda_runtime.h>
#include <cuda_fp16.h>
#include <math.h>
#include <stdint.h>

#define H     24
#define LIMG  2048
#define LIP   512
#define DMOD  3072
#define DIP   1280
#define HD    128
#define LTOT  2560
#define KT    64
#define NIT2  20                // key tiles per split (LTOT/2/KT)
#define SCALE2 0.1275174735772347f
#define ONES2 0x3C003C00u

// ================= scratch =================
__device__ float  g_e[2 * DIP];
__device__ __half g_ipnorm_h[LIP * DIP];
__device__ __half g_Wh[2 * (size_t)DMOD * DIP];
__device__ float  g_ipk_raw[LIP * DMOD];
__device__ __half g_Vh[(size_t)H * LTOT * HD];         // fp16 [h][key][d] (K-layout)
__device__ __half g_Qh[(size_t)H * LIMG * HD];
__device__ __half g_Kh[(size_t)H * LTOT * HD];
__device__ float  g_Opart[2][(size_t)H * LIMG * HD];   // split-K partial O (fp32)
__device__ float  g_ML[2][(size_t)H * LIMG * 2];       // per-row (m, l)

__device__ __forceinline__ uint32_t s2u(const void* p) {
    uint32_t a;
    asm("{ .reg .u64 t; cvta.to.shared.u64 t, %1; cvt.u32.u64 %0, t; }" : "=r"(a) : "l"(p));
    return a;
}
__device__ __forceinline__ uint32_t pkh(float a, float b) {
    __half2 h = __floats2half2_rn(a, b);
    return *reinterpret_cast<uint32_t*>(&h);
}
__device__ __forceinline__ uint32_t pk2(float lo, float hi) {
    uint32_t d;
    asm("cvt.rn.f16x2.f32 %0, %1, %2;" : "=r"(d) : "f"(hi), "f"(lo));
    return d;
}
__device__ __forceinline__ uint32_t hex2(uint32_t x) {
    uint32_t d;
    asm("ex2.approx.f16x2 %0, %1;" : "=r"(d) : "r"(x));
    return d;
}
__device__ __forceinline__ float ex2(float x) {
    float y;
    asm("ex2.approx.f32 %0, %1;" : "=f"(y) : "f"(x));
    return y;
}
__device__ __forceinline__ void mma_f16(float* c, const uint32_t* a, uint32_t b0, uint32_t b1) {
    asm volatile("mma.sync.aligned.m16n8k16.row.col.f32.f16.f16.f32 "
        "{%0,%1,%2,%3}, {%4,%5,%6,%7}, {%8,%9}, {%0,%1,%2,%3};"
        : "+f"(c[0]), "+f"(c[1]), "+f"(c[2]), "+f"(c[3])
        : "r"(a[0]), "r"(a[1]), "r"(a[2]), "r"(a[3]), "r"(b0), "r"(b1));
}
__device__ __forceinline__ void ldsm4(uint32_t* r, uint32_t addr) {
    asm volatile("ldmatrix.sync.aligned.m8n8.x4.shared.b16 {%0,%1,%2,%3}, [%4];"
        : "=r"(r[0]), "=r"(r[1]), "=r"(r[2]), "=r"(r[3]) : "r"(addr));
}
__device__ __forceinline__ void ldsm4t(uint32_t* r, uint32_t addr) {
    asm volatile("ldmatrix.sync.aligned.m8n8.x4.trans.shared.b16 {%0,%1,%2,%3}, [%4];"
        : "=r"(r[0]), "=r"(r[1]), "=r"(r[2]), "=r"(r[3]) : "r"(addr));
}
__device__ __forceinline__ void cp16(uint32_t dst, const void* src) {
    asm volatile("cp.async.cg.shared.global [%0], [%1], 16;" :: "r"(dst), "l"(src));
}

extern __shared__ __align__(16) char dynsm[];

// ================= stage 1: ada ================
__global__ void ada_kernel(const float* __restrict__ t_emb,
                           const float* __restrict__ w_ada,
                           const float* __restrict__ b_ada) {
    int o = blockIdx.x * 8 + (threadIdx.x >> 5);
    int lane = threadIdx.x & 31;
    if (o >= 2 * DIP) return;
    const float* w = w_ada + (size_t)o * DIP;
    float s = 0.f;
    for (int i = lane; i < DIP; i += 32) {
        float t = t_emb[i];
        s += (t / (1.f + expf(-t))) * w[i];
    }
#pragma unroll
    for (int off = 16; off; off >>= 1) s += __shfl_xor_sync(0xffffffffu, s, off);
    if (lane == 0) g_e[o] = s + b_ada[o];
}

// ================= stage 2: AdaLN -> fp16 ================
__global__ void adaln_kernel(const float* __restrict__ ip) {
    int row = blockIdx.x;
    const float* x = ip + (size_t)row * DIP;
    __shared__ float red1[8], red2[8];
    float s = 0.f, s2 = 0.f;
    for (int i = threadIdx.x; i < DIP; i += 256) {
        float v = x[i]; s += v; s2 += v * v;
    }
#pragma unroll
    for (int off = 16; off; off >>= 1) {
        s  += __shfl_xor_sync(0xffffffffu, s, off);
        s2 += __shfl_xor_sync(0xffffffffu, s2, off);
    }
    int w = threadIdx.x >> 5, lane = threadIdx.x & 31;
    if (lane == 0) { red1[w] = s; red2[w] = s2; }
    __syncthreads();
    float ts = 0.f, ts2 = 0.f;
#pragma unroll
    for (int i = 0; i < 8; i++) { ts += red1[i]; ts2 += red2[i]; }
    float mu = ts / DIP;
    float inv = rsqrtf(ts2 / DIP - mu * mu + 1e-6f);
    for (int i = threadIdx.x; i < DIP; i += 256) {
        float xn = (x[i] - mu) * inv;
        g_ipnorm_h[(size_t)row * DIP + i] = __float2half(xn * (1.f + g_e[DIP + i]) + g_e[i]);
    }
}

// ================= stage 2b: weight fp32 -> fp16 ================
__global__ void wconv_kernel(const float* __restrict__ wk, const float* __restrict__ wv) {
    size_t i = ((size_t)blockIdx.x * 256 + threadIdx.x) * 4;
    const float* src = blockIdx.y ? wv : wk;
    __half* dst = g_Wh + (size_t)blockIdx.y * DMOD * DIP;
    float4 f = *(const float4*)(src + i);
    uint2 u = { pkh(f.x, f.y), pkh(f.z, f.w) };
    *(uint2*)(dst + i) = u;
}

// ================= stage 3: fused ip GEMM, CTA 128x96, 2 CTA/SM ==============
// 4 warps as 2x2 (warp tile 64m x 48n); grid 64 x 4 = 256 CTAs (< 1 wave @2/SM)
// SMEM: A 2x(128x144B)=36864 | B 2x(96x144B)=27648 -> 64512 B
#define GEMM_SMEM 64512

__device__ __forceinline__ void gemm_issue(uint32_t sb, int tid, int bm, int bn,
                                           int ks, int buf) {
#pragma unroll
    for (int n = 0; n < 8; n++) {
        int i = tid + n * 128;
        int row = i >> 3, c = i & 7;
        cp16(sb + buf * 18432 + row * 144 + c * 16,
             g_ipnorm_h + (size_t)(bm + row) * DIP + ks * 64 + c * 8);
    }
#pragma unroll
    for (int n = 0; n < 6; n++) {
        int i = tid + n * 128;
        int row = i >> 3, c = i & 7;
        cp16(sb + 36864 + buf * 13824 + row * 144 + c * 16,
             g_Wh + (size_t)(bn + row) * DIP + ks * 64 + c * 8);
    }
    asm volatile("cp.async.commit_group;");
}

__global__ void __launch_bounds__(128, 2) ip_gemm_h_kernel() {
    const uint32_t sb = s2u(dynsm);
    const int tid = threadIdx.x;
    const int w = tid >> 5, t = tid & 31;
    const int r4 = t >> 2, q4 = t & 3;
    const int wr = w >> 1, wc = w & 1;     // 2x2 warp grid, warp tile 64m x 48n
    const int bn = blockIdx.x * 96, bm = blockIdx.y * 128;

    gemm_issue(sb, tid, bm, bn, 0, 0);
    gemm_issue(sb, tid, bm, bn, 1, 1);

    float oc[4][6][4] = {};
    const int rowselA = t & 15;
    const int winA = (t >> 4) << 4;
    const int rowselB = (t & 7) + ((t & 16) >> 1);
    const int winB = (t & 8) << 1;

    for (int ks = 0; ks < 20; ks++) {
        const int buf = ks & 1;
        if (ks < 18) asm volatile("cp.async.wait_group 1;");
        else         asm volatile("cp.async.wait_group 0;");
        __syncthreads();
        const uint32_t Ab = sb + buf * 18432;
        const uint32_t Bb = sb + 36864 + buf * 13824;
#pragma unroll
        for (int kb = 0; kb < 4; kb++) {
            uint32_t aa[4][4];
#pragma unroll
            for (int mb = 0; mb < 4; mb++)
                ldsm4(aa[mb], Ab + (wr * 64 + mb * 16 + rowselA) * 144 + kb * 32 + winA);
#pragma unroll
            for (int nb = 0; nb < 3; nb++) {
                uint32_t bb[4];
                ldsm4(bb, Bb + (wc * 48 + nb * 16 + rowselB) * 144 + kb * 32 + winB);
#pragma unroll
                for (int mb = 0; mb < 4; mb++) {
                    mma_f16(oc[mb][2 * nb],     aa[mb], bb[0], bb[1]);
                    mma_f16(oc[mb][2 * nb + 1], aa[mb], bb[2], bb[3]);
                }
            }
        }
        __syncthreads();
        if (ks + 2 < 20) gemm_issue(sb, tid, bm, bn, ks + 2, buf);
        else asm volatile("cp.async.commit_group;");
    }

#pragma unroll
    for (int mb = 0; mb < 4; mb++) {
        const int m_lo = bm + wr * 64 + mb * 16 + r4, m_hi = m_lo + 8;
#pragma unroll
        for (int nbp = 0; nbp < 6; nbp++) {
            int n = bn + wc * 48 + nbp * 8 + q4 * 2;
            if (n < DMOD) {
                float2 vlo = { oc[mb][nbp][0], oc[mb][nbp][1] };
                float2 vhi = { oc[mb][nbp][2], oc[mb][nbp][3] };
                *(float2*)(g_ipk_raw + (size_t)m_lo * DMOD + n) = vlo;
                *(float2*)(g_ipk_raw + (size_t)m_hi * DMOD + n) = vhi;
            } else {
                int nn = n - DMOD;
                int hh = nn >> 7, dd = nn & 127;
                *(uint32_t*)(g_Vh + ((size_t)hh * LTOT + LIMG + m_lo) * HD + dd) =
                    pkh(oc[mb][nbp][0], oc[mb][nbp][1]);
                *(uint32_t*)(g_Vh + ((size_t)hh * LTOT + LIMG + m_hi) * HD + dd) =
                    pkh(oc[mb][nbp][2], oc[mb][nbp][3]);
            }
        }
    }
}

// ================= stage 4: RMS + fp16 pack ================
__device__ __forceinline__ float warp_sum(float s) {
#pragma unroll
    for (int off = 16; off; off >>= 1) s += __shfl_xor_sync(0xffffffffu, s, off);
    return s;
}
__device__ __forceinline__ void st_h4(__half* p, float a, float b, float c, float d) {
    uint2 u = { pkh(a, b), pkh(c, d) };
    *reinterpret_cast<uint2*>(p) = u;
}

__global__ void qkv_rms_kernel(const float* __restrict__ q,
                               const float* __restrict__ k,
                               const float* __restrict__ v,
                               const float* __restrict__ gq,
                               const float* __restrict__ gk) {
    int rid = blockIdx.x * 8 + (threadIdx.x >> 5);
    if (rid >= LIMG * H) return;
    int lane = threadIdx.x & 31;
    int l = rid / H, hh = rid % H;
    size_t src = (size_t)l * DMOD + hh * HD + lane * 4;

    float4 xv = *(const float4*)(q + src);
    float inv = rsqrtf(warp_sum(xv.x*xv.x + xv.y*xv.y + xv.z*xv.z + xv.w*xv.w) / 128.f + 1e-6f) * SCALE2;
    float4 gv = ((const float4*)gq)[lane];
    st_h4(g_Qh + ((size_t)hh * LIMG + l) * HD + lane * 4,
          xv.x*inv*gv.x, xv.y*inv*gv.y, xv.z*inv*gv.z, xv.w*inv*gv.w);

    xv = *(const float4*)(k + src);
    inv = rsqrtf(warp_sum(xv.x*xv.x + xv.y*xv.y + xv.z*xv.z + xv.w*xv.w) / 128.f + 1e-6f);
    gv = ((const float4*)gk)[lane];
    st_h4(g_Kh + ((size_t)hh * LTOT + l) * HD + lane * 4,
          xv.x*inv*gv.x, xv.y*inv*gv.y, xv.z*inv*gv.z, xv.w*inv*gv.w);

    xv = *(const float4*)(v + src);
    st_h4(g_Vh + ((size_t)hh * LTOT + l) * HD + lane * 4, xv.x, xv.y, xv.z, xv.w);
}

__global__ void ipk_rms_kernel(const float* __restrict__ gipk) {
    int rid = blockIdx.x * 8 + (threadIdx.x >> 5);
    if (rid >= LIP * H) return;
    int lane = threadIdx.x & 31;
    int l = rid / H, hh = rid % H;
    float4 xv = *(const float4*)(g_ipk_raw + (size_t)l * DMOD + hh * HD + lane * 4);
    float inv = rsqrtf(warp_sum(xv.x*xv.x + xv.y*xv.y + xv.z*xv.z + xv.w*xv.w) / 128.f + 1e-6f);
    float4 gv = ((const float4*)gipk)[lane];
    st_h4(g_Kh + ((size_t)hh * LTOT + LIMG + l) * HD + lane * 4,
          xv.x*inv*gv.x, xv.y*inv*gv.y, xv.z*inv*gv.z, xv.w*inv*gv.w);
}

// ================= stage 5: flash attention, Br=128, split-K x2 ==============
// V key-major via ldmatrix.trans; Q loaded via cp.async (own group).
// SMEM: Q 128x272B | K 2x(64x272B) | V 2x(64x272B) = 104448 B (2 CTA/SM)
#define SQ_OFF  0
#define SK_OFF  34816
#define SK_BUF  17408
#define SV_OFF  (34816 + 2 * 17408)     // 69632
#define SV_BUF  17408
#define ATTN_SMEM (SV_OFF + 2 * SV_BUF) // 104448

__global__ void __launch_bounds__(128, 2) attn_kernel() {
    char* smem = dynsm;
    const uint32_t sb = s2u(smem);
    const int tid = threadIdx.x;
    const int w = tid >> 5, t = tid & 31;
    const int r4 = t >> 2, q4 = t & 3;
    const int hh = blockIdx.y, q0 = blockIdx.x * 128, z = blockIdx.z;
    const int k0 = z * (LTOT / 2);

    const int rowselA = t & 15;
    const int winA = (t >> 4) << 4;
    const int rowselB = (t & 7) + ((t & 16) >> 1);
    const int winB = (t & 8) << 1;
    const int rowV = (t & 7) + (t & 8);
    const int colV = (t & 16);

    // ---- Q tile via cp.async (group 0) ----
    const __half* qgb = g_Qh + ((size_t)hh * LIMG + q0) * HD;
#pragma unroll
    for (int n = 0; n < 16; n++) {
        int i = tid + n * 128;
        int rr = i >> 4, cc = i & 15;
        cp16(sb + SQ_OFF + rr * 272 + cc * 16, qgb + (size_t)rr * HD + cc * 8);
    }
    asm volatile("cp.async.commit_group;");

    const __half* kgb = g_Kh + ((size_t)hh * LTOT + k0) * HD;
    const __half* vgb = g_Vh + ((size_t)hh * LTOT + k0) * HD;
#pragma unroll
    for (int pb = 0; pb < 2; pb++) {
        for (int n = 0; n < 8; n++) {
            int i = tid + n * 128;
            int kr = i >> 4, c = i & 15;
            cp16(sb + SK_OFF + pb * SK_BUF + kr * 272 + c * 16,
                 kgb + ((size_t)(pb * KT + kr)) * HD + c * 8);
            cp16(sb + SV_OFF + pb * SV_BUF + kr * 272 + c * 16,
                 vgb + ((size_t)(pb * KT + kr)) * HD + c * 8);
        }
        asm volatile("cp.async.commit_group;");
    }

    float m[2][2] = {{-1e30f, -1e30f}, {-1e30f, -1e30f}};
    float oc[2][16][4];
#pragma unroll
    for (int mb = 0; mb < 2; mb++)
#pragma unroll
        for (int nb = 0; nb < 16; nb++)
#pragma unroll
            for (int j = 0; j < 4; j++) oc[mb][nb][j] = 0.f;
    float lacc[2][4] = {};

    const uint32_t Qb = sb + SQ_OFF;

    for (int it = 0; it < NIT2; it++) {
        const int b = it & 1;
        asm volatile("cp.async.wait_group 1;");
        __syncthreads();

        float sc[2][8][4];
#pragma unroll
        for (int mb = 0; mb < 2; mb++)
#pragma unroll
            for (int nb = 0; nb < 8; nb++)
#pragma unroll
                for (int j = 0; j < 4; j++) sc[mb][nb][j] = 0.f;
        const uint32_t Kb = sb + SK_OFF + b * SK_BUF;
#pragma unroll
        for (int kb = 0; kb < 8; kb++) {
            uint32_t qa0[4], qa1[4];
            ldsm4(qa0, Qb + (w * 32 + rowselA) * 272 + kb * 32 + winA);
            ldsm4(qa1, Qb + (w * 32 + 16 + rowselA) * 272 + kb * 32 + winA);
#pragma unroll
            for (int nb2 = 0; nb2 < 4; nb2++) {
                uint32_t bb[4];
                ldsm4(bb, Kb + (nb2 * 16 + rowselB) * 272 + kb * 32 + winB);
                mma_f16(sc[0][2 * nb2],     qa0, bb[0], bb[1]);
                mma_f16(sc[0][2 * nb2 + 1], qa0, bb[2], bb[3]);
                mma_f16(sc[1][2 * nb2],     qa1, bb[0], bb[1]);
                mma_f16(sc[1][2 * nb2 + 1], qa1, bb[2], bb[3]);
            }
        }

        float mn[2][2];
#pragma unroll
        for (int mb = 0; mb < 2; mb++) {
            float mt_lo = -1e30f, mt_hi = -1e30f;
#pragma unroll
            for (int n = 0; n < 8; n++) {
                mt_lo = fmaxf(mt_lo, fmaxf(sc[mb][n][0], sc[mb][n][1]));
                mt_hi = fmaxf(mt_hi, fmaxf(sc[mb][n][2], sc[mb][n][3]));
            }
            mt_lo = fmaxf(mt_lo, __shfl_xor_sync(0xffffffffu, mt_lo, 1));
            mt_lo = fmaxf(mt_lo, __shfl_xor_sync(0xffffffffu, mt_lo, 2));
            mt_hi = fmaxf(mt_hi, __shfl_xor_sync(0xffffffffu, mt_hi, 1));
            mt_hi = fmaxf(mt_hi, __shfl_xor_sync(0xffffffffu, mt_hi, 2));
            mn[mb][0] = fmaxf(m[mb][0], mt_lo);
            mn[mb][1] = fmaxf(m[mb][1], mt_hi);
        }
        bool upd = (mn[0][0] > m[0][0]) | (mn[0][1] > m[0][1]) |
                   (mn[1][0] > m[1][0]) | (mn[1][1] > m[1][1]);
        if (__any_sync(0xffffffffu, upd)) {
#pragma unroll
            for (int mb = 0; mb < 2; mb++) {
                float co_lo = ex2(m[mb][0] - mn[mb][0]);
                float co_hi = ex2(m[mb][1] - mn[mb][1]);
#pragma unroll
                for (int nb = 0; nb < 16; nb++) {
                    oc[mb][nb][0] *= co_lo; oc[mb][nb][1] *= co_lo;
                    oc[mb][nb][2] *= co_hi; oc[mb][nb][3] *= co_hi;
                }
                lacc[mb][0] *= co_lo; lacc[mb][1] *= co_lo;
                lacc[mb][2] *= co_hi; lacc[mb][3] *= co_hi;
            }
        }
#pragma unroll
        for (int mb = 0; mb < 2; mb++) { m[mb][0] = mn[mb][0]; m[mb][1] = mn[mb][1]; }

        const uint32_t Vb = sb + SV_OFF + b * SV_BUF;
#pragma unroll
        for (int kbg = 0; kbg < 4; kbg++) {
            uint32_t pa0[4], pa1[4];
            pa0[0] = hex2(pk2(sc[0][2*kbg][0]   - m[0][0], sc[0][2*kbg][1]   - m[0][0]));
            pa0[1] = hex2(pk2(sc[0][2*kbg][2]   - m[0][1], sc[0][2*kbg][3]   - m[0][1]));
            pa0[2] = hex2(pk2(sc[0][2*kbg+1][0] - m[0][0], sc[0][2*kbg+1][1] - m[0][0]));
            pa0[3] = hex2(pk2(sc[0][2*kbg+1][2] - m[0][1], sc[0][2*kbg+1][3] - m[0][1]));
            pa1[0] = hex2(pk2(sc[1][2*kbg][0]   - m[1][0], sc[1][2*kbg][1]   - m[1][0]));
            pa1[1] = hex2(pk2(sc[1][2*kbg][2]   - m[1][1], sc[1][2*kbg][3]   - m[1][1]));
            pa1[2] = hex2(pk2(sc[1][2*kbg+1][0] - m[1][0], sc[1][2*kbg+1][1] - m[1][0]));
            pa1[3] = hex2(pk2(sc[1][2*kbg+1][2] - m[1][1], sc[1][2*kbg+1][3] - m[1][1]));

            mma_f16(lacc[0], pa0, ONES2, ONES2);
            mma_f16(lacc[1], pa1, ONES2, ONES2);

#pragma unroll
            for (int nb2 = 0; nb2 < 8; nb2++) {
                uint32_t bb[4];
                ldsm4t(bb, Vb + (kbg * 16 + rowV) * 272 + nb2 * 32 + colV);
                mma_f16(oc[0][2 * nb2],     pa0, bb[0], bb[1]);
                mma_f16(oc[0][2 * nb2 + 1], pa0, bb[2], bb[3]);
                mma_f16(oc[1][2 * nb2],     pa1, bb[0], bb[1]);
                mma_f16(oc[1][2 * nb2 + 1], pa1, bb[2], bb[3]);
            }
        }
        __syncthreads();

        if (it + 2 < NIT2) {
            for (int n = 0; n < 8; n++) {
                int i = tid + n * 128;
                int kr = i >> 4, c = i & 15;
                cp16(sb + SK_OFF + b * SK_BUF + kr * 272 + c * 16,
                     kgb + ((size_t)((it + 2) * KT + kr)) * HD + c * 8);
                cp16(sb + SV_OFF + b * SV_BUF + kr * 272 + c * 16,
                     vgb + ((size_t)((it + 2) * KT + kr)) * HD + c * 8);
            }
        }
        asm volatile("cp.async.commit_group;");
    }

    // ---- epilogue: fp32 unnormalized partials + (m, l) ----
    float* ob = g_Opart[z] + ((size_t)hh * LIMG + q0) * HD;
#pragma unroll
    for (int mb = 0; mb < 2; mb++) {
        float* orow_lo = ob + (size_t)(w * 32 + mb * 16 + r4) * HD + 2 * q4;
        float* orow_hi = orow_lo + 8 * HD;
#pragma unroll
        for (int nb = 0; nb < 16; nb++) {
            float2 vlo = { oc[mb][nb][0], oc[mb][nb][1] };
            float2 vhi = { oc[mb][nb][2], oc[mb][nb][3] };
            *(float2*)(orow_lo + nb * 8) = vlo;
            *(float2*)(orow_hi + nb * 8) = vhi;
        }
        if (q4 == 0) {
            size_t row = (size_t)hh * LIMG + q0 + w * 32 + mb * 16 + r4;
            g_ML[z][row * 2]           = m[mb][0];
            g_ML[z][row * 2 + 1]       = lacc[mb][0];
            g_ML[z][(row + 8) * 2]     = m[mb][1];
            g_ML[z][(row + 8) * 2 + 1] = lacc[mb][2];
        }
    }
}

// ================= stage 6: split-K combine ==================================
__global__ void attn_reduce_kernel(float* __restrict__ out) {
    size_t gidx = (size_t)blockIdx.x * 256 + threadIdx.x;
    size_t row = gidx >> 5;
    int chunk = (int)(gidx & 31);
    int hh = (int)(row / LIMG), q = (int)(row % LIMG);
    float m0 = g_ML[0][row * 2], l0 = g_ML[0][row * 2 + 1];
    float m1 = g_ML[1][row * 2], l1 = g_ML[1][row * 2 + 1];
    float ms = fmaxf(m0, m1);
    float c0 = ex2(m0 - ms), c1 = ex2(m1 - ms);
    float inv = 1.f / (l0 * c0 + l1 * c1);
    float4 o0 = *(const float4*)(g_Opart[0] + row * HD + chunk * 4);
    float4 o1 = *(const float4*)(g_Opart[1] + row * HD + chunk * 4);
    float4 r = { (o0.x * c0 + o1.x * c1) * inv,
                 (o0.y * c0 + o1.y * c1) * inv,
                 (o0.z * c0 + o1.z * c1) * inv,
                 (o0.w * c0 + o1.w * c1) * inv };
    *(float4*)(out + (size_t)q * DMOD + hh * HD + chunk * 4) = r;
}

// ================= launch =====================================================
extern "C" void kernel_launch(void* const* d_in, const int* in_sizes, int n_in,
                              void* d_out, int out_size) {
    const float* ip   = (const float*)d_in[0];
    const float* q    = (const float*)d_in[1];
    const float* k    = (const float*)d_in[2];
    const float* v    = (const float*)d_in[3];
    const float* temb = (const float*)d_in[4];
    const float* wada = (const float*)d_in[5];
    const float* bada = (const float*)d_in[6];
    const float* wk   = (const float*)d_in[7];
    const float* wv   = (const float*)d_in[8];
    const float* gq   = (const float*)d_in[9];
    const float* gk   = (const float*)d_in[10];
    const float* gipk = (const float*)d_in[11];
    float* out = (float*)d_out;

    ada_kernel<<<(2 * DIP + 7) / 8, 256>>>(temb, wada, bada);
    adaln_kernel<<<LIP, 256>>>(ip);
    wconv_kernel<<<dim3(DMOD * DIP / 1024, 2), 256>>>(wk, wv);

    cudaFuncSetAttribute(ip_gemm_h_kernel, cudaFuncAttributeMaxDynamicSharedMemorySize, GEMM_SMEM);
    ip_gemm_h_kernel<<<dim3(DMOD * 2 / 96, LIP / 128), 128, GEMM_SMEM>>>();

    qkv_rms_kernel<<<(LIMG * H + 7) / 8, 256>>>(q, k, v, gq, gk);
    ipk_rms_kernel<<<(LIP * H + 7) / 8, 256>>>(gipk);

    cudaFuncSetAttribute(attn_kernel, cudaFuncAttributeMaxDynamicSharedMemorySize, ATTN_SMEM);
    attn_kernel<<<dim3(LIMG / 128, H, 2), 128, ATTN_SMEM>>>();

    attn_reduce_kernel<<<(H * LIMG * HD / 4) / 256, 256>>>(out);
}